// round 3
// baseline (speedup 1.0000x reference)
#include <cuda_runtime.h>
#include <cuda_bf16.h>

// Levinson-Durbin, M=24. TWO rows per thread via Blackwell packed f32x2 math.
// out[row] = [K, a0..a23],  R a = -r1,  K = sqrt(E_24).
//
// R2 changes vs best (R0):
//  - fma.rn.f32x2 / mul.rn.f32x2 / add.rn.f32x2: one instruction drives two
//    independent rows -> per-row dynamic instruction count ~halved (the
//    kernel was issue-bound at 52% issue).
//  - rcp pipelined one iteration ahead (MUFU latency hidden); negation folded
//    into the MUFU operand (rcp(-E) = -1/E).
//  - E update via identity E*(1-k^2) == fmaf(k, acc, E).
//  - __launch_bounds__(256,2): 128-reg cap, fits ~120 live regs w/o spills.

constexpr int M_ORD = 24;
constexpr int NC    = M_ORD + 1;     // 25
constexpr int TPB   = 256;
constexpr int RPB   = 512;           // rows per block (2 per thread)
constexpr int SV4   = TPB * NC / 4;  // 1600 float4 per 256-row stage

using u64 = unsigned long long;

__device__ __forceinline__ u64 pack2(float lo, float hi) {
    u64 d; asm("mov.b64 %0, {%1, %2};" : "=l"(d) : "f"(lo), "f"(hi)); return d;
}
__device__ __forceinline__ void unpack2(u64 x, float& lo, float& hi) {
    asm("mov.b64 {%0, %1}, %2;" : "=f"(lo), "=f"(hi) : "l"(x));
}
__device__ __forceinline__ u64 fma2(u64 a, u64 b, u64 c) {
    u64 d; asm("fma.rn.f32x2 %0, %1, %2, %3;" : "=l"(d) : "l"(a), "l"(b), "l"(c)); return d;
}
__device__ __forceinline__ u64 mul2(u64 a, u64 b) {
    u64 d; asm("mul.rn.f32x2 %0, %1, %2;" : "=l"(d) : "l"(a), "l"(b)); return d;
}
__device__ __forceinline__ u64 add2(u64 a, u64 b) {
    u64 d; asm("add.rn.f32x2 %0, %1, %2;" : "=l"(d) : "l"(a), "l"(b)); return d;
}
// -(1/x): negation folded into MUFU operand
__device__ __forceinline__ float nrcp(float x) {
    float y; asm("rcp.approx.f32 %0, %1;" : "=f"(y) : "f"(-x)); return y;
}

__global__ __launch_bounds__(TPB, 2)
void levinson_durbin_kernel(const float* __restrict__ r,
                            float* __restrict__ out,
                            int nrows)
{
    __shared__ float sbuf[TPB * NC];   // 25600 B (one 256-row stage)
    const int tid  = threadIdx.x;
    const int row0 = blockIdx.x * RPB;
    const bool full_block = (row0 + RPB) <= nrows;

    u64 rr[NC];

    if (full_block) {
        float tmp[NC];
        float4* s4 = reinterpret_cast<float4*>(sbuf);
        // stage A: rows [row0, row0+256)  (lo lanes)
        const float4* gA = reinterpret_cast<const float4*>(r + (size_t)row0 * NC);
        #pragma unroll
        for (int i = tid; i < SV4; i += TPB) s4[i] = gA[i];
        __syncthreads();
        #pragma unroll
        for (int i = 0; i < NC; i++) tmp[i] = sbuf[tid * NC + i];
        __syncthreads();
        // stage B: rows [row0+256, row0+512)  (hi lanes)
        const float4* gB = reinterpret_cast<const float4*>(r + (size_t)(row0 + TPB) * NC);
        #pragma unroll
        for (int i = tid; i < SV4; i += TPB) s4[i] = gB[i];
        __syncthreads();
        #pragma unroll
        for (int i = 0; i < NC; i++) rr[i] = pack2(tmp[i], sbuf[tid * NC + i]);
        // each thread re-writes only its own cells afterwards -> no sync here
    } else {
        const int ra = row0 + tid;
        const int rb = row0 + TPB + tid;
        #pragma unroll
        for (int i = 0; i < NC; i++) {
            float lo = (ra < nrows) ? r[(size_t)ra * NC + i] : (i == 0 ? 1.0f : 0.0f);
            float hi = (rb < nrows) ? r[(size_t)rb * NC + i] : (i == 0 ? 1.0f : 0.0f);
            rr[i] = pack2(lo, hi);
        }
    }

    // ---- packed Levinson-Durbin recursion (both lanes independent) ----
    u64 a[M_ORD];
    u64 E = rr[0];
    u64 ninvE;                         // packed { -1/E_lo, -1/E_hi }
    {
        float el, eh; unpack2(E, el, eh);
        ninvE = pack2(nrcp(el), nrcp(eh));
    }

    #pragma unroll
    for (int m = 0; m < M_ORD; m++) {
        // dot: acc = rr[m+1] + sum_i a[i]*rr[m-i]   (2-way split accumulators)
        u64 s0 = rr[m + 1];
        u64 s1 = 0ULL;                 // {+0.f, +0.f}
        #pragma unroll
        for (int i = 0; i + 1 < m; i += 2) {
            s0 = fma2(a[i    ], rr[m - i    ], s0);
            s1 = fma2(a[i + 1], rr[m - i - 1], s1);
        }
        if (m & 1) s0 = fma2(a[m - 1], rr[1], s0);
        u64 acc = add2(s0, s1);

        // k = -acc / E  (ninvE precomputed last iteration; MUFU hidden)
        u64 k = mul2(acc, ninvE);

        // symmetric in-place update: a_i' = a_i + k * a_{m-1-i}
        #pragma unroll
        for (int i = 0; i < m / 2; i++) {
            u64 t = a[i];
            u64 u = a[m - 1 - i];
            a[i]         = fma2(k, u, t);
            a[m - 1 - i] = fma2(k, t, u);
        }
        if (m & 1) {
            u64 t = a[m / 2];
            a[m / 2] = fma2(k, t, t);
        }
        a[m] = k;

        // E *= (1 - k^2)  ==  E + k*acc
        E = fma2(k, acc, E);
        float el, eh; unpack2(E, el, eh);
        ninvE = pack2(nrcp(el), nrcp(eh));   // hides under next dot
    }

    float el, eh; unpack2(E, el, eh);
    const float Klo = sqrtf(el);
    const float Khi = sqrtf(eh);

    if (full_block) {
        float4* s4 = reinterpret_cast<float4*>(sbuf);
        // lo lanes -> rows [row0, row0+256)
        sbuf[tid * NC + 0] = Klo;
        #pragma unroll
        for (int i = 0; i < M_ORD; i++) {
            float lo, hi; unpack2(a[i], lo, hi);
            sbuf[tid * NC + 1 + i] = lo;
        }
        __syncthreads();
        float4* oA = reinterpret_cast<float4*>(out + (size_t)row0 * NC);
        #pragma unroll
        for (int i = tid; i < SV4; i += TPB) oA[i] = s4[i];
        __syncthreads();
        // hi lanes -> rows [row0+256, row0+512)
        sbuf[tid * NC + 0] = Khi;
        #pragma unroll
        for (int i = 0; i < M_ORD; i++) {
            float lo, hi; unpack2(a[i], lo, hi);
            sbuf[tid * NC + 1 + i] = hi;
        }
        __syncthreads();
        float4* oB = reinterpret_cast<float4*>(out + (size_t)(row0 + TPB) * NC);
        #pragma unroll
        for (int i = tid; i < SV4; i += TPB) oB[i] = s4[i];
    } else {
        const int ra = row0 + tid;
        const int rb = row0 + TPB + tid;
        if (ra < nrows) {
            out[(size_t)ra * NC + 0] = Klo;
            #pragma unroll
            for (int i = 0; i < M_ORD; i++) {
                float lo, hi; unpack2(a[i], lo, hi);
                out[(size_t)ra * NC + 1 + i] = lo;
            }
        }
        if (rb < nrows) {
            out[(size_t)rb * NC + 0] = Khi;
            #pragma unroll
            for (int i = 0; i < M_ORD; i++) {
                float lo, hi; unpack2(a[i], lo, hi);
                out[(size_t)rb * NC + 1 + i] = hi;
            }
        }
    }
}

extern "C" void kernel_launch(void* const* d_in, const int* in_sizes, int n_in,
                              void* d_out, int out_size)
{
    const float* r = (const float*)d_in[0];
    float* out = (float*)d_out;
    const int nrows = in_sizes[0] / NC;
    const int grid = (nrows + RPB - 1) / RPB;
    levinson_durbin_kernel<<<grid, TPB>>>(r, out, nrows);
}

// round 4
// speedup vs baseline: 1.1602x; 1.1602x over previous
#include <cuda_runtime.h>
#include <cuda_bf16.h>

// Levinson-Durbin, M=24. 2 rows per thread (sequential, scalar math).
// out[row] = [K, a0..a23],  R a = -r1,  K = sqrt(E_24).
//
// R3 design:
//  - TPB=64, 128 rows/CTA, grid=2048 -> all 131072 threads resident in ONE
//    wave (885 thr/SM < 1024-thread reg cap), ~1.2% CTA imbalance.
//  - cp.async double-buffer: both tiles prefetched at kernel start;
//    wait_group 1 lets tile-A compute overlap tile-B's copy.
//  - output staged into the consumed input buffer (smem reuse, 12.8KB/CTA).
//  - recursion: 4-split dot accumulators, pipelined rcp(-E), E += k*acc.

constexpr int M_ORD = 24;
constexpr int NC    = M_ORD + 1;            // 25
constexpr int TPB   = 64;
constexpr int ROWS_PER_TILE = TPB;          // 64
constexpr int RPB   = 2 * ROWS_PER_TILE;    // 128 rows per CTA
constexpr int TILE_FLOATS = ROWS_PER_TILE * NC;  // 1600
constexpr int TILE_V4     = TILE_FLOATS / 4;     // 400

__device__ __forceinline__ void cp_async16(unsigned saddr, const void* gaddr) {
    asm volatile("cp.async.cg.shared.global [%0], [%1], 16;"
                 :: "r"(saddr), "l"(gaddr));
}
__device__ __forceinline__ void cp_commit() {
    asm volatile("cp.async.commit_group;");
}
template <int N>
__device__ __forceinline__ void cp_wait() {
    asm volatile("cp.async.wait_group %0;" :: "n"(N));
}
// -(1/x): negation folded into the MUFU operand
__device__ __forceinline__ float nrcp(float x) {
    float y; asm("rcp.approx.f32 %0, %1;" : "=f"(y) : "f"(-x)); return y;
}

// Full Levinson-Durbin recursion; returns K = sqrt(E_M), fills a[0..23].
__device__ __forceinline__ float levdur(const float rr[NC], float a[M_ORD]) {
    float E     = rr[0];
    float ninvE = nrcp(E);                  // -1/E (pipelined one iter ahead)
    #pragma unroll
    for (int m = 0; m < M_ORD; m++) {
        // acc = rr[m+1] + sum_i a[i]*rr[m-i], 4-way split accumulators
        float s0 = rr[m + 1], s1 = 0.0f, s2 = 0.0f, s3 = 0.0f;
        #pragma unroll
        for (int i = 0; i + 3 < m; i += 4) {
            s0 = fmaf(a[i    ], rr[m - i    ], s0);
            s1 = fmaf(a[i + 1], rr[m - i - 1], s1);
            s2 = fmaf(a[i + 2], rr[m - i - 2], s2);
            s3 = fmaf(a[i + 3], rr[m - i - 3], s3);
        }
        {
            int i = m & ~3;
            if (i     < m) s0 = fmaf(a[i    ], rr[m - i    ], s0);
            if (i + 1 < m) s1 = fmaf(a[i + 1], rr[m - i - 1], s1);
            if (i + 2 < m) s2 = fmaf(a[i + 2], rr[m - i - 2], s2);
        }
        float acc = (s0 + s1) + (s2 + s3);

        float k = acc * ninvE;              // k = -acc/E (MUFU latency hidden)

        // symmetric in-place update: a_i' = a_i + k * a_{m-1-i}
        #pragma unroll
        for (int i = 0; i < m / 2; i++) {
            float t = a[i];
            float u = a[m - 1 - i];
            a[i]         = fmaf(k, u, t);
            a[m - 1 - i] = fmaf(k, t, u);
        }
        if (m & 1) {
            float t = a[m / 2];
            a[m / 2] = fmaf(k, t, t);
        }
        a[m] = k;

        E     = fmaf(k, acc, E);            // E *= (1 - k^2)
        ninvE = nrcp(E);                    // hides under next dot
    }
    return sqrtf(E);
}

__global__ __launch_bounds__(TPB, 16)
void levinson_durbin_kernel(const float* __restrict__ r,
                            float* __restrict__ out,
                            int nrows)
{
    __shared__ float sbuf[2][TILE_FLOATS];  // 12.8 KB
    const int tid  = threadIdx.x;
    const int row0 = blockIdx.x * RPB;

    float rr[NC];
    float a[M_ORD];

    if (row0 + RPB <= nrows) {
        // ---- async prefetch of both 64-row tiles ----
        unsigned s0 = (unsigned)__cvta_generic_to_shared(&sbuf[0][0]);
        unsigned s1 = (unsigned)__cvta_generic_to_shared(&sbuf[1][0]);
        const float4* g0 = reinterpret_cast<const float4*>(r + (size_t)row0 * NC);
        const float4* g1 = reinterpret_cast<const float4*>(r + (size_t)(row0 + ROWS_PER_TILE) * NC);
        #pragma unroll
        for (int i = tid; i < TILE_V4; i += TPB) cp_async16(s0 + i * 16, g0 + i);
        cp_commit();
        #pragma unroll
        for (int i = tid; i < TILE_V4; i += TPB) cp_async16(s1 + i * 16, g1 + i);
        cp_commit();

        // ---- tile A: wait for its copy only (tile B still in flight) ----
        cp_wait<1>();
        __syncthreads();
        #pragma unroll
        for (int i = 0; i < NC; i++) rr[i] = sbuf[0][tid * NC + i];

        float Kv = levdur(rr, a);

        // stage output A into the consumed buffer (own row only: no sync needed)
        sbuf[0][tid * NC + 0] = Kv;
        #pragma unroll
        for (int i = 0; i < M_ORD; i++) sbuf[0][tid * NC + 1 + i] = a[i];

        cp_wait<0>();                        // tile B data complete
        __syncthreads();                     // outA visible + B visible

        // coalesced store of tile A; tile B register load proceeds after
        float4* o0 = reinterpret_cast<float4*>(out + (size_t)row0 * NC);
        const float4* sb0 = reinterpret_cast<const float4*>(&sbuf[0][0]);
        #pragma unroll
        for (int i = tid; i < TILE_V4; i += TPB) o0[i] = sb0[i];

        // ---- tile B ----
        #pragma unroll
        for (int i = 0; i < NC; i++) rr[i] = sbuf[1][tid * NC + i];

        Kv = levdur(rr, a);

        sbuf[1][tid * NC + 0] = Kv;
        #pragma unroll
        for (int i = 0; i < M_ORD; i++) sbuf[1][tid * NC + 1 + i] = a[i];
        __syncthreads();

        float4* o1 = reinterpret_cast<float4*>(out + (size_t)(row0 + ROWS_PER_TILE) * NC);
        const float4* sb1 = reinterpret_cast<const float4*>(&sbuf[1][0]);
        #pragma unroll
        for (int i = tid; i < TILE_V4; i += TPB) o1[i] = sb1[i];
    } else {
        // generic tail path (not hit for BATCH=262144)
        #pragma unroll
        for (int t = 0; t < 2; t++) {
            int row = row0 + t * ROWS_PER_TILE + tid;
            if (row < nrows) {
                #pragma unroll
                for (int i = 0; i < NC; i++) rr[i] = r[(size_t)row * NC + i];
                float Kv = levdur(rr, a);
                out[(size_t)row * NC + 0] = Kv;
                #pragma unroll
                for (int i = 0; i < M_ORD; i++)
                    out[(size_t)row * NC + 1 + i] = a[i];
            }
        }
    }
}

extern "C" void kernel_launch(void* const* d_in, const int* in_sizes, int n_in,
                              void* d_out, int out_size)
{
    const float* r = (const float*)d_in[0];
    float* out = (float*)d_out;
    const int nrows = in_sizes[0] / NC;
    const int grid = (nrows + RPB - 1) / RPB;
    levinson_durbin_kernel<<<grid, TPB>>>(r, out, nrows);
}